// round 6
// baseline (speedup 1.0000x reference)
#include <cuda_runtime.h>
#include <cuda_bf16.h>
#include <math.h>
#include <stdint.h>

#define BN 4
#define HH 128
#define WW 128
#define HWS (HH * WW)
#define CC 64
#define O1 64
#define O2 32
#define NOFF 27
#define NPIX (BN * HWS)
#define TP 128
#define ST 72              // smem row stride in bf16 elems (144B)
#define STB 144

// deform kernel smem offsets
#define SM_AH   0
#define SM_AL   18432
#define SM_BH   36864
#define SM_BL   46080
#define SM_SWT  55296
#define SM_SIDX 57344
#define SM_TOTAL 59392

// offconv window kernel smem offsets
#define SM_WAH  0                       // 3*130*144 = 56160
#define SM_WAL  56160
#define SM_WBH  112320                  // 9*32*144 = 41472
#define SM_WBL  153792
#define SM_WTOT 195264

// ---------------- device scratch ----------------
__device__ float g_x2[BN * CC * HWS];
__device__ float g_off[BN * NOFF * HWS];
__device__ __nv_bfloat16 g_w1h[9 * O1 * CC];
__device__ __nv_bfloat16 g_w1l[9 * O1 * CC];
__device__ __nv_bfloat16 g_w2h[9 * O2 * CC];
__device__ __nv_bfloat16 g_w2l[9 * O2 * CC];
__device__ __nv_bfloat16 g_o1h[9 * O2 * CC];
__device__ __nv_bfloat16 g_o1l[9 * O2 * CC];
__device__ __nv_bfloat16 g_o2h[9 * O2 * CC];
__device__ __nv_bfloat16 g_o2l[9 * O2 * CC];
__device__ float g_b1[O1];
__device__ float g_b2[O2];

// ---------------- helpers ----------------
__device__ __forceinline__ unsigned smem_u32(const void* p) {
    unsigned a;
    asm("{ .reg .u64 t; cvta.to.shared.u64 t, %1; cvt.u32.u64 %0, t; }" : "=r"(a) : "l"(p));
    return a;
}
__device__ __forceinline__ void ldsm4(unsigned* r, unsigned addr) {
    asm volatile("ldmatrix.sync.aligned.m8n8.x4.shared.b16 {%0,%1,%2,%3}, [%4];"
                 : "=r"(r[0]), "=r"(r[1]), "=r"(r[2]), "=r"(r[3]) : "r"(addr));
}
__device__ __forceinline__ void mma16816(float* c, const unsigned* a, unsigned b0, unsigned b1) {
    asm volatile(
        "mma.sync.aligned.m16n8k16.row.col.f32.bf16.bf16.f32 "
        "{%0,%1,%2,%3}, {%4,%5,%6,%7}, {%8,%9}, {%0,%1,%2,%3};"
        : "+f"(c[0]), "+f"(c[1]), "+f"(c[2]), "+f"(c[3])
        : "r"(a[0]), "r"(a[1]), "r"(a[2]), "r"(a[3]), "r"(b0), "r"(b1));
}
__device__ __forceinline__ unsigned bf16x2_rn(float lo, float hi) {
    unsigned r;
    asm("cvt.rn.bf16x2.f32 %0, %1, %2;" : "=r"(r) : "f"(hi), "f"(lo));
    return r;
}

// ---------------- prep (weights only) ----------------
__global__ void prep_kernel(
    const float* __restrict__ wo1,
    const float* __restrict__ w1, const float* __restrict__ g1,
    const float* __restrict__ be1, const float* __restrict__ rm1, const float* __restrict__ rv1,
    const float* __restrict__ wo2,
    const float* __restrict__ w2, const float* __restrict__ g2,
    const float* __restrict__ be2, const float* __restrict__ rm2, const float* __restrict__ rv2)
{
    int t = blockIdx.x * blockDim.x + threadIdx.x;
    int stride = gridDim.x * blockDim.x;

    for (int i = t; i < 9 * O1 * CC; i += stride) {
        int c = i & 63;
        int o = (i >> 6) & 63;
        int k = i >> 12;
        float inv = g1[o] * rsqrtf(rv1[o] + 1e-5f);
        float v = w1[(o * CC + c) * 9 + k] * inv;
        __nv_bfloat16 hb = __float2bfloat16(v);
        g_w1h[i] = hb;
        g_w1l[i] = __float2bfloat16(v - __bfloat162float(hb));
    }
    for (int i = t; i < 9 * O2 * CC; i += stride) {
        int c = i & 63;
        int o = (i >> 6) & 31;
        int k = i >> 11;
        float inv = g2[o] * rsqrtf(rv2[o] + 1e-5f);
        float v = w2[(o * CC + c) * 9 + k] * inv;
        __nv_bfloat16 hb = __float2bfloat16(v);
        g_w2h[i] = hb;
        g_w2l[i] = __float2bfloat16(v - __bfloat162float(hb));
    }
    for (int i = t; i < 9 * O2 * CC; i += stride) {
        int c = i & 63;
        int o = (i >> 6) & 31;
        int k = i >> 11;
        float v1 = (o < NOFF) ? wo1[(o * CC + c) * 9 + k] : 0.f;
        float v2 = (o < NOFF) ? wo2[(o * CC + c) * 9 + k] : 0.f;
        __nv_bfloat16 h1 = __float2bfloat16(v1);
        __nv_bfloat16 h2 = __float2bfloat16(v2);
        g_o1h[i] = h1; g_o1l[i] = __float2bfloat16(v1 - __bfloat162float(h1));
        g_o2h[i] = h2; g_o2l[i] = __float2bfloat16(v2 - __bfloat162float(h2));
    }
    if (t < O1) { float inv = g1[t] * rsqrtf(rv1[t] + 1e-5f); g_b1[t] = be1[t] - rm1[t] * inv; }
    if (t < O2) { float inv = g2[t] * rsqrtf(rv2[t] + 1e-5f); g_b2[t] = be2[t] - rm2[t] * inv; }
}

// ---------------- offset conv: window-staged, all 9 taps from smem ----------------
// inputs xA (ch 0-31), xB (ch 32-63), each [b][32][HWS] with batch stride bstr
__global__ __launch_bounds__(256, 1)
void offconv_win_kernel(const float* __restrict__ xA, const float* __restrict__ xB,
                        long bstr,
                        const __nv_bfloat16* __restrict__ wh,
                        const __nv_bfloat16* __restrict__ wl,
                        const float* __restrict__ bias)
{
    extern __shared__ __align__(16) char sm[];
    const unsigned sb = smem_u32(sm);

    const int tid = threadIdx.x;
    const int wid = tid >> 5;
    const int lid = tid & 31;

    const int b  = blockIdx.x >> 7;
    const int h  = blockIdx.x & 127;
    const int sl = h * WW;

    // ---- stage A window: 3 rows x 130 px x 64 ch, hi/lo bf16 ----
    {
        const float* baseA = xA + b * bstr;
        const float* baseB = xB + b * bstr;
        // elements as channel-pairs: 3*130*32 = 12480
        for (int i = tid; i < 3 * 130 * 32; i += 256) {
            int cp = (i & 31) * 2;            // channel pair base
            int pp = (i >> 5) % 130;          // window pixel
            int y  = (i >> 5) / 130;          // window row
            int gy = h + y - 1;
            int gx = pp - 1;
            float v0 = 0.f, v1 = 0.f;
            if (gy >= 0 && gy < HH && gx >= 0 && gx < WW) {
                const float* src = ((cp < 32) ? baseA + cp * HWS
                                              : baseB + (cp - 32) * HWS) + gy * WW + gx;
                v0 = __ldg(src);
                v1 = __ldg(src + HWS);
            }
            unsigned hw = bf16x2_rn(v0, v1);
            float h0 = __uint_as_float(hw << 16);
            float h1 = __uint_as_float(hw & 0xFFFF0000u);
            unsigned lw = bf16x2_rn(v0 - h0, v1 - h1);
            unsigned boff = (unsigned)((y * 130 + pp) * STB + cp * 2);
            *(unsigned*)(sm + SM_WAH + boff) = hw;
            *(unsigned*)(sm + SM_WAL + boff) = lw;
        }
    }
    // ---- stage all 9 B chunks ----
    {
        const unsigned* shp = (const unsigned*)wh;
        const unsigned* slp = (const unsigned*)wl;
        for (int i = tid; i < 9 * 32 * 32; i += 256) {
            int kw = i & 31;
            int row = i >> 5;                  // tap*32 + n
            unsigned d = (unsigned)(row * STB + kw * 4);
            *(unsigned*)(sm + SM_WBH + d) = __ldg(shp + i);
            *(unsigned*)(sm + SM_WBL + d) = __ldg(slp + i);
        }
    }
    __syncthreads();

    const int lrow = lid & 15;
    const int lkof = (lid >> 4) * 8;
    const int pr = wid * 16 + lrow;            // output pixel row in A frags

    float acc[4][4];
#pragma unroll
    for (int i = 0; i < 4; i++)
#pragma unroll
        for (int j = 0; j < 4; j++) acc[i][j] = 0.f;

#pragma unroll 1
    for (int k = 0; k < 9; k++) {
        int ky = k / 3;                        // 0..2 window row
        int kx = k % 3 - 1;
        unsigned a_row = sb + (unsigned)((ky * 130 + pr + 1 + kx) * STB + lkof * 2);
        unsigned b_rowbase = sb + (unsigned)((k * 32 + lrow) * STB + lkof * 2);
#pragma unroll
        for (int q = 0; q < 4; q++) {
            unsigned ah[4], al[4];
            ldsm4(ah, a_row + SM_WAH + q * 32);
            ldsm4(al, a_row + SM_WAL + q * 32);
#pragma unroll
            for (int nf = 0; nf < 2; nf++) {
                unsigned bh[4], bl[4];
                unsigned b_addr = b_rowbase + (unsigned)(nf * 16 * STB + q * 32);
                ldsm4(bh, b_addr + SM_WBH);
                ldsm4(bl, b_addr + SM_WBL);
                mma16816(acc[nf * 2],     ah, bh[0], bh[2]);
                mma16816(acc[nf * 2 + 1], ah, bh[1], bh[3]);
                mma16816(acc[nf * 2],     ah, bl[0], bl[2]);
                mma16816(acc[nf * 2 + 1], ah, bl[1], bl[3]);
                mma16816(acc[nf * 2],     al, bh[0], bh[2]);
                mma16816(acc[nf * 2 + 1], al, bh[1], bh[3]);
            }
        }
    }

    // ---- epilogue: write 27 offset channels (sigmoid on 18..26) ----
    const int gm = lid >> 2;
    const int gn = (lid & 3) * 2;
    const int g0 = sl + wid * 16 + gm;
    const int g1i = g0 + 8;

#pragma unroll
    for (int nf = 0; nf < 4; nf++) {
        int o = nf * 8 + gn;
#pragma unroll
        for (int e = 0; e < 2; e++) {
            int oo = o + e;
            if (oo < NOFF) {
                float bb = __ldg(bias + oo);
                float v0 = acc[nf][e] + bb;
                float v1 = acc[nf][e + 2] + bb;
                if (oo >= 18) {
                    v0 = 1.f / (1.f + expf(-v0));
                    v1 = 1.f / (1.f + expf(-v1));
                }
                g_off[(b * NOFF + oo) * HWS + g0]  = v0;
                g_off[(b * NOFF + oo) * HWS + g1i] = v1;
            }
        }
    }
}

// ---------------- deform conv via mma.sync bf16x3 ----------------
// MODE 1: bias+relu -> out ; MODE 2: bias+relu, *(1-Aatt)*Batt -> out
template <int N, int MODE>
__global__ __launch_bounds__(256, 2)
void conv_mma_kernel(const float* __restrict__ xA, const float* __restrict__ xB,
                     long bstr,
                     const __nv_bfloat16* __restrict__ wh,
                     const __nv_bfloat16* __restrict__ wl,
                     const float* __restrict__ bias,
                     float* __restrict__ out,
                     const float* __restrict__ Aatt,
                     const float* __restrict__ Batt)
{
    extern __shared__ __align__(16) char sm[];
    const unsigned sb = smem_u32(sm);

    const int tid = threadIdx.x;
    const int wid = tid >> 5;
    const int lid = tid & 31;

    const int b  = blockIdx.x >> 7;
    const int h  = blockIdx.x & 127;
    const int sl = h * WW;

    float* swt  = (float*)(sm + SM_SWT);
    int*   sidx = (int*)(sm + SM_SIDX);

    const int p  = tid & 127;
    const float* xc = ((tid >> 7) == 0) ? (xA + b * bstr) : (xB + b * bstr);

    constexpr int NF16 = N / 16;
    float acc[N / 8][4];
#pragma unroll
    for (int i = 0; i < N / 8; i++)
#pragma unroll
        for (int j = 0; j < 4; j++) acc[i][j] = 0.f;

    const int lrow = lid & 15;
    const int lkof = (lid >> 4) * 8;
    const unsigned a_base = sb + ((wid * 16 + lrow) * ST + lkof) * 2;

#pragma unroll 1
    for (int k = 0; k < 9; k++) {
        if (tid < TP) {
            const float* op = g_off + b * NOFF * HWS + sl + tid;
            float dy = op[(2 * k) * HWS];
            float dx = op[(2 * k + 1) * HWS];
            float m  = op[(18 + k) * HWS];       // pre-sigmoided

            float ys = (float)(h + (k / 3 - 1)) + dy;
            float xs = (float)(tid + (k % 3 - 1)) + dx;
            float y0f = floorf(ys), x0f = floorf(xs);
            float fy = ys - y0f, fx = xs - x0f;
            int y0 = (int)y0f, x0 = (int)x0f;
            int y1 = y0 + 1, x1 = x0 + 1;

            float vy0 = (y0 >= 0 && y0 < HH) ? m : 0.f;
            float vy1 = (y1 >= 0 && y1 < HH) ? m : 0.f;
            float vx0 = (x0 >= 0 && x0 < WW) ? 1.f : 0.f;
            float vx1 = (x1 >= 0 && x1 < WW) ? 1.f : 0.f;

            swt[0 * TP + tid] = (1.f - fy) * (1.f - fx) * vy0 * vx0;
            swt[1 * TP + tid] = (1.f - fy) * fx * vy0 * vx1;
            swt[2 * TP + tid] = fy * (1.f - fx) * vy1 * vx0;
            swt[3 * TP + tid] = fy * fx * vy1 * vx1;

            int cy0 = min(max(y0, 0), HH - 1), cy1 = min(max(y1, 0), HH - 1);
            int cx0 = min(max(x0, 0), WW - 1), cx1 = min(max(x1, 0), WW - 1);
            sidx[0 * TP + tid] = cy0 * WW + cx0;
            sidx[1 * TP + tid] = cy0 * WW + cx1;
            sidx[2 * TP + tid] = cy1 * WW + cx0;
            sidx[3 * TP + tid] = cy1 * WW + cx1;
        }
        __syncthreads();

        // ---- stage A (hi/lo bf16) ----
        {
            float w00 = swt[p], w01 = swt[TP + p], w10 = swt[2 * TP + p], w11 = swt[3 * TP + p];
            int i00 = sidx[p], i01 = sidx[TP + p], i10 = sidx[2 * TP + p], i11 = sidx[3 * TP + p];
            const int cb = (tid >> 7) * 32;
#pragma unroll 4
            for (int j = 0; j < 16; j++) {
                const float* x0p = xc + (2 * j) * HWS;
                const float* x1p = x0p + HWS;
                float v0 = w00 * __ldg(x0p + i00) + w01 * __ldg(x0p + i01)
                         + w10 * __ldg(x0p + i10) + w11 * __ldg(x0p + i11);
                float v1 = w00 * __ldg(x1p + i00) + w01 * __ldg(x1p + i01)
                         + w10 * __ldg(x1p + i10) + w11 * __ldg(x1p + i11);
                unsigned hw = bf16x2_rn(v0, v1);
                float h0 = __uint_as_float(hw << 16);
                float h1 = __uint_as_float(hw & 0xFFFF0000u);
                unsigned lw = bf16x2_rn(v0 - h0, v1 - h1);
                unsigned boff = (unsigned)(p * ST + cb + 2 * j) * 2u;
                *(unsigned*)(sm + SM_AH + boff) = hw;
                *(unsigned*)(sm + SM_AL + boff) = lw;
            }
        }

        // ---- stage B ----
        {
            const unsigned* shp = (const unsigned*)(wh + k * (N * CC));
            const unsigned* slp = (const unsigned*)(wl + k * (N * CC));
            for (int i = tid; i < N * 32; i += 256) {
                int n = i >> 5, kw = i & 31;
                ((unsigned*)(sm + SM_BH))[n * (ST / 2) + kw] = __ldg(shp + i);
                ((unsigned*)(sm + SM_BL))[n * (ST / 2) + kw] = __ldg(slp + i);
            }
        }
        __syncthreads();

#pragma unroll
        for (int q = 0; q < 4; q++) {
            unsigned ah[4], al[4];
            ldsm4(ah, a_base + SM_AH + q * 32);
            ldsm4(al, a_base + SM_AL + q * 32);
#pragma unroll
            for (int nf = 0; nf < NF16; nf++) {
                unsigned bh[4], bl[4];
                unsigned b_base = sb + ((nf * 16 + lrow) * ST + q * 16 + lkof) * 2;
                ldsm4(bh, b_base + SM_BH);
                ldsm4(bl, b_base + SM_BL);
                mma16816(acc[nf * 2],     ah, bh[0], bh[2]);
                mma16816(acc[nf * 2 + 1], ah, bh[1], bh[3]);
                mma16816(acc[nf * 2],     ah, bl[0], bl[2]);
                mma16816(acc[nf * 2 + 1], ah, bl[1], bl[3]);
                mma16816(acc[nf * 2],     al, bh[0], bh[2]);
                mma16816(acc[nf * 2 + 1], al, bh[1], bh[3]);
            }
        }
        __syncthreads();
    }

    // ---- epilogue ----
    const int gm = lid >> 2;
    const int gn = (lid & 3) * 2;
    const int g0 = sl + wid * 16 + gm;
    const int g1i = g0 + 8;

    float ga0 = 1.f, ga1 = 1.f;
    if (MODE == 2) {
        ga0 = (1.f - __ldg(Aatt + b * HWS + g0)) * __ldg(Batt + b * HWS + g0);
        ga1 = (1.f - __ldg(Aatt + b * HWS + g1i)) * __ldg(Batt + b * HWS + g1i);
    }

#pragma unroll
    for (int nf = 0; nf < N / 8; nf++) {
        int o = nf * 8 + gn;
#pragma unroll
        for (int e = 0; e < 2; e++) {
            int oo = o + e;
            float bb = __ldg(bias + oo);
            float v0 = fmaxf(acc[nf][e] + bb, 0.f);
            float v1 = fmaxf(acc[nf][e + 2] + bb, 0.f);
            if (MODE == 2) { v0 *= ga0; v1 *= ga1; }
            out[(b * N + oo) * HWS + g0]  = v0;
            out[(b * N + oo) * HWS + g1i] = v1;
        }
    }
}

// ---------------- launch ----------------
extern "C" void kernel_launch(void* const* d_in, const int* in_sizes, int n_in,
                              void* d_out, int out_size)
{
    const float* pA   = (const float*)d_in[1];
    const float* pB   = (const float*)d_in[2];
    const float* Aatt = (const float*)d_in[3];
    const float* Batt = (const float*)d_in[4];
    const float* wo1  = (const float*)d_in[5];
    const float* bo1  = (const float*)d_in[6];
    const float* w1   = (const float*)d_in[7];
    const float* g1   = (const float*)d_in[8];
    const float* be1  = (const float*)d_in[9];
    const float* rm1  = (const float*)d_in[10];
    const float* rv1  = (const float*)d_in[11];
    const float* wo2  = (const float*)d_in[12];
    const float* bo2  = (const float*)d_in[13];
    const float* w2   = (const float*)d_in[14];
    const float* g2   = (const float*)d_in[15];
    const float* be2  = (const float*)d_in[16];
    const float* rm2  = (const float*)d_in[17];
    const float* rv2  = (const float*)d_in[18];

    float *x2, *pb1, *pb2;
    __nv_bfloat16 *w1h, *w1l, *w2h, *w2l, *o1h, *o1l, *o2h, *o2l;
    cudaGetSymbolAddress((void**)&x2,  g_x2);
    cudaGetSymbolAddress((void**)&pb1, g_b1);
    cudaGetSymbolAddress((void**)&pb2, g_b2);
    cudaGetSymbolAddress((void**)&w1h, g_w1h);
    cudaGetSymbolAddress((void**)&w1l, g_w1l);
    cudaGetSymbolAddress((void**)&w2h, g_w2h);
    cudaGetSymbolAddress((void**)&w2l, g_w2l);
    cudaGetSymbolAddress((void**)&o1h, g_o1h);
    cudaGetSymbolAddress((void**)&o1l, g_o1l);
    cudaGetSymbolAddress((void**)&o2h, g_o2h);
    cudaGetSymbolAddress((void**)&o2l, g_o2l);

    cudaFuncSetAttribute(offconv_win_kernel, cudaFuncAttributeMaxDynamicSharedMemorySize, SM_WTOT);
    cudaFuncSetAttribute(conv_mma_kernel<64, 1>, cudaFuncAttributeMaxDynamicSharedMemorySize, SM_TOTAL);
    cudaFuncSetAttribute(conv_mma_kernel<32, 2>, cudaFuncAttributeMaxDynamicSharedMemorySize, SM_TOTAL);

    dim3 blk(256);
    dim3 grd(NPIX / TP);   // 512
    const long s32 = 32L * HWS;   // batch stride for pA/pB halves
    const long s64 = 64L * HWS;   // batch stride for x2

    prep_kernel<<<64, 256>>>(wo1, w1, g1, be1, rm1, rv1,
                             wo2, w2, g2, be2, rm2, rv2);

    // layer 1: channels 0-31 = pB, 32-63 = pA
    offconv_win_kernel<<<grd, blk, SM_WTOT>>>(pB, pA, s32, o1h, o1l, bo1);
    conv_mma_kernel<64, 1><<<grd, blk, SM_TOTAL>>>(pB, pA, s32, w1h, w1l, pb1, x2, nullptr, nullptr);
    // layer 2: x2 halves
    offconv_win_kernel<<<grd, blk, SM_WTOT>>>(x2, x2 + 32 * HWS, s64, o2h, o2l, bo2);
    conv_mma_kernel<32, 2><<<grd, blk, SM_TOTAL>>>(x2, x2 + 32 * HWS, s64, w2h, w2l, pb2,
                                                   (float*)d_out, Aatt, Batt);
}